// round 9
// baseline (speedup 1.0000x reference)
#include <cuda_runtime.h>
#include <cuda_bf16.h>
#include <math.h>
#include <stdint.h>

#define Bsz   8192
#define Ddim  512
#define Kneg  2048
#define NPAD  4096
#define EPSN  1e-8f
#define INV254 (1.0f / 254.0f)

// ================= scratch =================
__device__ float  g_C[(size_t)Bsz * NPAD];
__device__ int8_t g_Ah[(size_t)Bsz * Ddim];
__device__ int8_t g_Al[(size_t)Bsz * Ddim];
__device__ int8_t g_Bh[(size_t)NPAD * Ddim];
__device__ int8_t g_Bl[(size_t)NPAD * Ddim];
__device__ float  g_sA[Bsz];
__device__ float  g_sB[NPAD];
__device__ float g_ni[Bsz], g_nj[Bsz], g_plog[Bsz];
__device__ int   g_mark[Bsz], g_slot[Bsz];
__device__ int   g_Ulist[NPAD];           // zero-init; pad slots stay 0 forever
__device__ int   g_map0[Kneg], g_map1[Kneg];
__device__ float g_nj0[Kneg], g_nj1[Kneg];
__device__ int   g_Ucnt;                  // reset by final_kernel each replay
__device__ float g_loss[Bsz];
__device__ int   g_cnt[Bsz];

// ================= PTX helpers =================
__device__ __forceinline__ uint32_t smem_u32(const void* p) {
    uint32_t a;
    asm("{ .reg .u64 t; cvta.to.shared.u64 t, %1; cvt.u32.u64 %0, t; }" : "=r"(a) : "l"(p));
    return a;
}
__device__ __forceinline__ void cp16(uint32_t dst, const void* src) {
    asm volatile("cp.async.cg.shared.global [%0], [%1], 16;" :: "r"(dst), "l"(src));
}
__device__ __forceinline__ void cp_commit() { asm volatile("cp.async.commit_group;"); }
__device__ __forceinline__ void cp_wait1()  { asm volatile("cp.async.wait_group 1;" ::: "memory"); }
__device__ __forceinline__ void cp_wait0()  { asm volatile("cp.async.wait_group 0;" ::: "memory"); }
__device__ __forceinline__ void ldsm_x4(uint32_t addr, uint32_t& r0, uint32_t& r1,
                                        uint32_t& r2, uint32_t& r3) {
    asm volatile("ldmatrix.sync.aligned.m8n8.x4.shared.b16 {%0,%1,%2,%3}, [%4];"
                 : "=r"(r0), "=r"(r1), "=r"(r2), "=r"(r3) : "r"(addr));
}
__device__ __forceinline__ void mma_s8(int d[4], const uint32_t a[4], const uint32_t b[2]) {
    asm volatile(
        "mma.sync.aligned.m16n8k32.row.col.s32.s8.s8.s32 "
        "{%0,%1,%2,%3}, {%4,%5,%6,%7}, {%8,%9}, {%0,%1,%2,%3};"
        : "+r"(d[0]), "+r"(d[1]), "+r"(d[2]), "+r"(d[3])
        : "r"(a[0]), "r"(a[1]), "r"(a[2]), "r"(a[3]), "r"(b[0]), "r"(b[1]));
}

// ================= 0. assign: dedup marks + atomic slot assignment =================
// Slot order nondeterministic but every output bit is slot-independent.
__global__ void assign_kernel(const int* __restrict__ perm) {
    int k = blockIdx.x * blockDim.x + threadIdx.x;
    if (k >= Kneg) return;
    int p = perm[k];
#pragma unroll
    for (int t = 0; t < 2; t++) {
        int x = p + t;
        if (atomicExch(&g_mark[x], 1) == 0) {
            int s = atomicAdd(&g_Ucnt, 1);
            g_slot[x] = s;
            g_Ulist[s] = x;
        }
    }
}

// ================= 1. norms + positive logit =================
__global__ void norms_kernel(const float* __restrict__ zi, const float* __restrict__ zj) {
    int warp = (blockIdx.x * blockDim.x + threadIdx.x) >> 5;
    int lane = threadIdx.x & 31;
    if (warp >= Bsz) return;
    const float4* a = (const float4*)(zi + (size_t)warp * Ddim);
    const float4* b = (const float4*)(zj + (size_t)warp * Ddim);
    float si = 0.f, sj = 0.f, dij = 0.f;
#pragma unroll
    for (int c = 0; c < 4; c++) {
        float4 x = a[c * 32 + lane];
        float4 y = b[c * 32 + lane];
        si  += x.x*x.x + x.y*x.y + x.z*x.z + x.w*x.w;
        sj  += y.x*y.x + y.y*y.y + y.z*y.z + y.w*y.w;
        dij += x.x*y.x + x.y*y.y + x.z*y.z + x.w*y.w;
    }
#pragma unroll
    for (int o = 16; o > 0; o >>= 1) {
        si  += __shfl_down_sync(0xffffffffu, si, o);
        sj  += __shfl_down_sync(0xffffffffu, sj, o);
        dij += __shfl_down_sync(0xffffffffu, dij, o);
    }
    if (lane == 0) {
        float ni = sqrtf(si), nj = sqrtf(sj);
        g_ni[warp] = ni;
        g_nj[warp] = nj;
        g_plog[warp] = dij / fmaxf(ni * nj, EPSN) * 2.0f;
    }
}

// ================= 2. fused quantize (A, gathered B) + maps =================
// One warp per row: s = max|x|/127; h = rint(x/s); l = rint((x/s - h)*254).
__device__ __forceinline__ void quant_row(const float* __restrict__ src,
                                          int8_t* __restrict__ hdst,
                                          int8_t* __restrict__ ldst,
                                          float* __restrict__ sdst,
                                          int out_row, int lane) {
    const float4* s4 = (const float4*)(src + lane * 16);
    float4 v[4];
    float mx = 0.f;
#pragma unroll
    for (int c = 0; c < 4; c++) {
        v[c] = s4[c];
        mx = fmaxf(mx, fmaxf(fmaxf(fabsf(v[c].x), fabsf(v[c].y)),
                             fmaxf(fabsf(v[c].z), fabsf(v[c].w))));
    }
#pragma unroll
    for (int o = 16; o > 0; o >>= 1)
        mx = fmaxf(mx, __shfl_xor_sync(0xffffffffu, mx, o));
    float inv = (mx > 0.f) ? 127.0f / mx : 0.f;
    char h[16], l[16];
    const float* vf = (const float*)v;
#pragma unroll
    for (int q = 0; q < 16; q++) {
        float xs = vf[q] * inv;
        int hi = __float2int_rn(xs);
        float r = xs - (float)hi;
        int lo = __float2int_rn(r * 254.0f);
        h[q] = (char)hi;
        l[q] = (char)lo;
    }
    size_t off = (size_t)out_row * Ddim + lane * 16;
    *(uint4*)(hdst + off) = *(uint4*)h;
    *(uint4*)(ldst + off) = *(uint4*)l;
    if (lane == 0) sdst[out_row] = mx * (1.0f / 127.0f);
}

#define QA_BLOCKS  1024
#define QB_BLOCKS  512
#define MAP_BLOCKS 8

__global__ void prep_kernel(const float* __restrict__ zi, const float* __restrict__ zj,
                            const int* __restrict__ perm) {
    int blk = blockIdx.x;
    int tid = threadIdx.x;
    int w = tid >> 5, lane = tid & 31;
    if (blk < QA_BLOCKS) {
        int row = blk * 8 + w;
        quant_row(zi + (size_t)row * Ddim, g_Ah, g_Al, g_sA, row, lane);
    } else if (blk < QA_BLOCKS + QB_BLOCKS) {
        int u = (blk - QA_BLOCKS) * 8 + w;
        int row = g_Ulist[u];
        quant_row(zj + (size_t)row * Ddim, g_Bh, g_Bl, g_sB, u, lane);
    } else {
        int k = (blk - QA_BLOCKS - QB_BLOCKS) * 256 + tid;
        if (k < Kneg) {
            int p = perm[k];
            g_map0[k] = g_slot[p];
            g_map1[k] = g_slot[p + 1];
            g_nj0[k] = g_nj[p];
            g_nj1[k] = g_nj[p + 1];
        }
    }
}

// ================= 3. GEMM: int8 m16n8k32, 3-term fixed-point =================
// Block 128x128, 512 threads (16 warps), warp tile 32x32 (2 accs: HH and HL+LH).
// K chunks of 64 int8 (64B rows), 3-stage cp.async, XOR 16B-chunk swizzle.
#define QARRB 8192                   // 128 rows x 64B
#define QSTGB (4 * QARRB)            // 32768 B
#define QNSTG 3
#define QSMEM (QNSTG * QSTGB)        // 98304 B
#define QNCH  (Ddim / 64)            // 8

__global__ __launch_bounds__(512, 1) void gemm_s8_kernel() {
    const int n0 = blockIdx.x * 128;
    const int m0 = blockIdx.y * 128;
    if (n0 >= g_Ucnt) return;

    extern __shared__ char sm[];
    const uint32_t sb = smem_u32(sm);

    const int tid  = threadIdx.x;
    const int lane = tid & 31;
    const int wid  = tid >> 5;
    const int wm   = wid >> 2;        // 0..3 (32-row slice)
    const int wn   = wid & 3;         // 0..3 (32-col slice)

    // ---- cp.async: arr = tid>>7, 4 x 16B per thread per stage ----
    const int arr = tid >> 7;         // 0:Ah 1:Al 2:Bh 3:Bl
    const int lt  = tid & 127;        // row
    const int8_t* garr =
        (arr == 0) ? g_Ah + (size_t)m0 * Ddim :
        (arr == 1) ? g_Al + (size_t)m0 * Ddim :
        (arr == 2) ? g_Bh + (size_t)n0 * Ddim :
                     g_Bl + (size_t)n0 * Ddim;

    uint32_t st_dst[4];
    uint32_t st_src[4];
#pragma unroll
    for (int q = 0; q < 4; q++) {
        int phys = q ^ ((lt >> 1) & 3);
        st_dst[q] = (uint32_t)(arr * QARRB + lt * 64 + phys * 16);
        st_src[q] = (uint32_t)(lt * Ddim + q * 16);
    }

    // ldmatrix offsets (g=0 baseline; g=1 is addr ^ 32)
    uint32_t aoff[2];
#pragma unroll
    for (int mt = 0; mt < 2; mt++) {
        int row = wm * 32 + mt * 16 + (lane & 15);
        int phys = (lane >> 4) ^ ((row >> 1) & 3);
        aoff[mt] = (uint32_t)(row * 64 + phys * 16);
    }
    uint32_t boff[2];
#pragma unroll
    for (int p = 0; p < 2; p++) {
        int row = wn * 32 + p * 16 + (((lane >> 4) & 1) << 3) + (lane & 7);
        int phys = ((lane >> 3) & 1) ^ ((row >> 1) & 3);
        boff[p] = (uint32_t)(2 * QARRB + row * 64 + phys * 16);
    }

    int d0[2][4][4], d1[2][4][4];
#pragma unroll
    for (int mt = 0; mt < 2; mt++)
#pragma unroll
        for (int nt = 0; nt < 4; nt++)
#pragma unroll
            for (int q = 0; q < 4; q++) { d0[mt][nt][q] = 0; d1[mt][nt][q] = 0; }

    // prologue: chunks 0 and 1
#pragma unroll
    for (int ck = 0; ck < 2; ck++) {
        uint32_t stg = sb + ck * QSTGB;
#pragma unroll
        for (int q = 0; q < 4; q++)
            cp16(stg + st_dst[q], garr + ck * 64 + st_src[q]);
        cp_commit();
    }

    for (int c = 0; c < QNCH; c++) {
        if (c + 1 < QNCH) cp_wait1(); else cp_wait0();
        __syncthreads();

        if (c + 2 < QNCH) {
            uint32_t stg = sb + ((c + 2) % QNSTG) * QSTGB;
            const int8_t* gsrc = garr + (c + 2) * 64;
#pragma unroll
            for (int q = 0; q < 4; q++)
                cp16(stg + st_dst[q], gsrc + st_src[q]);
            cp_commit();
        }

        const uint32_t s0 = sb + (c % QNSTG) * QSTGB;
#pragma unroll
        for (int g = 0; g < 2; g++) {           // two k32 groups per k64 chunk
            const uint32_t gx = (uint32_t)(g * 32);
            uint32_t ah[2][4], al[2][4];
#pragma unroll
            for (int mt = 0; mt < 2; mt++) {
                uint32_t ra = s0 + (aoff[mt] ^ gx);
                ldsm_x4(ra,         ah[mt][0], ah[mt][1], ah[mt][2], ah[mt][3]);
                ldsm_x4(ra + QARRB, al[mt][0], al[mt][1], al[mt][2], al[mt][3]);
            }
#pragma unroll
            for (int p = 0; p < 2; p++) {       // pairs of n8 tiles
                uint32_t bh[4], bl[4];
                uint32_t rb = s0 + (boff[p] ^ gx);
                ldsm_x4(rb,         bh[0], bh[1], bh[2], bh[3]);
                ldsm_x4(rb + QARRB, bl[0], bl[1], bl[2], bl[3]);
#pragma unroll
                for (int mt = 0; mt < 2; mt++) {
#pragma unroll
                    for (int j = 0; j < 2; j++) {
                        int nt = p * 2 + j;
                        mma_s8(d0[mt][nt], ah[mt], bh + j * 2);
                        mma_s8(d1[mt][nt], ah[mt], bl + j * 2);
                        mma_s8(d1[mt][nt], al[mt], bh + j * 2);
                    }
                }
            }
        }
    }

    // ---- epilogue: C = sA*sB*(HH + (HL+LH)/254) ----
#pragma unroll
    for (int mt = 0; mt < 2; mt++) {
        int r0 = m0 + wm * 32 + mt * 16 + (lane >> 2);
        float sA0 = __ldg(&g_sA[r0]);
        float sA1 = __ldg(&g_sA[r0 + 8]);
#pragma unroll
        for (int nt = 0; nt < 4; nt++) {
            int col = n0 + wn * 32 + nt * 8 + (lane & 3) * 2;
            float sB0 = __ldg(&g_sB[col]);
            float sB1 = __ldg(&g_sB[col + 1]);
            const int* a0 = d0[mt][nt];
            const int* a1 = d1[mt][nt];
            float c00 = sA0 * sB0 * ((float)a0[0] + (float)a1[0] * INV254);
            float c01 = sA0 * sB1 * ((float)a0[1] + (float)a1[1] * INV254);
            float c10 = sA1 * sB0 * ((float)a0[2] + (float)a1[2] * INV254);
            float c11 = sA1 * sB1 * ((float)a0[3] + (float)a1[3] * INV254);
            float* p0 = g_C + (size_t)r0 * NPAD + col;
            float* p1 = g_C + (size_t)(r0 + 8) * NPAD + col;
            *(float2*)p0 = make_float2(c00, c01);
            *(float2*)p1 = make_float2(c10, c11);
        }
    }
}

// ================= 4. per-row logsumexp + rank counts =================
__global__ __launch_bounds__(256) void reduce_kernel(const int* __restrict__ perm) {
    __shared__ int   s_p[Kneg];
    __shared__ int   s_m0[Kneg];
    __shared__ int   s_m1[Kneg];
    __shared__ float s_n0[Kneg];
    __shared__ float s_n1[Kneg];
    __shared__ float redf[256];
    __shared__ int   redi[256];

    int tid = threadIdx.x;
    for (int k = tid; k < Kneg; k += 256) {
        s_p[k]  = perm[k];
        s_m0[k] = g_map0[k];
        s_m1[k] = g_map1[k];
        s_n0[k] = g_nj0[k];
        s_n1[k] = g_nj1[k];
    }
    __syncthreads();

    for (int r = 0; r < 8; r++) {
        int i = blockIdx.x * 8 + r;
        float ni = g_ni[i];
        float lp = g_plog[i];
        const float* Crow = g_C + (size_t)i * NPAD;

        float tmax = lp;
        for (int k = tid; k < Kneg; k += 256) {
            bool sel = (s_p[k] >= i);
            int slot  = sel ? s_m1[k] : s_m0[k];
            float njc = sel ? s_n1[k] : s_n0[k];
            float l = Crow[slot] / fmaxf(ni * njc, EPSN) * 2.0f;
            tmax = fmaxf(tmax, l);
        }
        redf[tid] = tmax;
        __syncthreads();
        for (int o = 128; o > 0; o >>= 1) {
            if (tid < o) redf[tid] = fmaxf(redf[tid], redf[tid + o]);
            __syncthreads();
        }
        float M = redf[0];
        __syncthreads();

        float s = 0.f;
        int cnt = 0;
        for (int k = tid; k < Kneg; k += 256) {
            bool sel = (s_p[k] >= i);
            int slot  = sel ? s_m1[k] : s_m0[k];
            float njc = sel ? s_n1[k] : s_n0[k];
            float l = Crow[slot] / fmaxf(ni * njc, EPSN) * 2.0f;
            s += expf(l - M);
            cnt += (l > lp) ? 1 : 0;
        }
        redf[tid] = s;
        redi[tid] = cnt;
        __syncthreads();
        for (int o = 128; o > 0; o >>= 1) {
            if (tid < o) { redf[tid] += redf[tid + o]; redi[tid] += redi[tid + o]; }
            __syncthreads();
        }
        if (tid == 0) {
            g_loss[i] = M + logf(redf[0] + expf(lp - M)) - lp;
            g_cnt[i]  = redi[0];
        }
        __syncthreads();
    }
}

// ================= 5. final reduction + state cleanup =================
__global__ void final_kernel(float* __restrict__ out) {
    __shared__ float sf[1024];
    __shared__ int   s1[1024];
    __shared__ int   s5[1024];
    int tid = threadIdx.x;
    float s = 0.f;
    int c1 = 0, c5 = 0;
    for (int i = tid; i < Bsz; i += 1024) {
        s += g_loss[i];
        int c = g_cnt[i];
        c1 += (c == 0) ? 1 : 0;
        c5 += (c <= 4) ? 1 : 0;
    }
    sf[tid] = s; s1[tid] = c1; s5[tid] = c5;
    __syncthreads();
    for (int o = 512; o > 0; o >>= 1) {
        if (tid < o) { sf[tid] += sf[tid + o]; s1[tid] += s1[tid + o]; s5[tid] += s5[tid + o]; }
        __syncthreads();
    }
    if (tid == 0) {
        out[0] = sf[0] / (float)Bsz;
        out[1] = 100.0f * (float)s1[0] / (float)Bsz;
        out[2] = 100.0f * (float)s5[0] / (float)Bsz;
        g_Ucnt = 0;                               // self-clean for next replay
    }
    for (int i = tid; i < Bsz; i += 1024) g_mark[i] = 0;
}

// ================= launch =================
extern "C" void kernel_launch(void* const* d_in, const int* in_sizes, int n_in,
                              void* d_out, int out_size) {
    const float* zi   = (const float*)d_in[0];
    const float* zj   = (const float*)d_in[1];
    const int*   perm = (const int*)d_in[2];
    float* out = (float*)d_out;

    cudaFuncSetAttribute(gemm_s8_kernel, cudaFuncAttributeMaxDynamicSharedMemorySize, QSMEM);

    assign_kernel<<<2, 1024>>>(perm);                                        // 0
    norms_kernel<<<Bsz / 8, 256>>>(zi, zj);                                  // 1
    prep_kernel<<<QA_BLOCKS + QB_BLOCKS + MAP_BLOCKS, 256>>>(zi, zj, perm);  // 2
    dim3 g(NPAD / 128, Bsz / 128);                                           // 32 x 64
    gemm_s8_kernel<<<g, 512, QSMEM>>>();                                     // 3 (ncu target)
    reduce_kernel<<<Bsz / 8, 256>>>(perm);                                   // 4
    final_kernel<<<1, 1024>>>(out);                                          // 5
}

// round 11
// speedup vs baseline: 1.6995x; 1.6995x over previous
#include <cuda_runtime.h>
#include <cuda_bf16.h>
#include <math.h>
#include <stdint.h>

#define Bsz   8192
#define Ddim  512
#define Kneg  2048
#define NPAD  4096
#define EPSN  1e-8f

// ================= scratch =================
__device__ float        g_C[(size_t)Bsz * NPAD];
__device__ __nv_bfloat16 g_Ahi[(size_t)Bsz * Ddim];
__device__ __nv_bfloat16 g_Alo[(size_t)Bsz * Ddim];
__device__ __nv_bfloat16 g_Bhi[(size_t)NPAD * Ddim];
__device__ __nv_bfloat16 g_Blo[(size_t)NPAD * Ddim];
__device__ float g_ni[Bsz], g_nj[Bsz], g_plog[Bsz];
__device__ int   g_mark[Bsz], g_slot[Bsz];
__device__ int   g_Ulist[NPAD];           // zero-init; pad slots stay 0 forever
__device__ int   g_map0[Kneg], g_map1[Kneg];
__device__ float g_nj0[Kneg], g_nj1[Kneg];
__device__ int   g_Ucnt;                  // reset by final_kernel each replay
__device__ float g_loss[Bsz];
__device__ int   g_cnt[Bsz];

// ================= PTX helpers =================
__device__ __forceinline__ uint32_t smem_u32(const void* p) {
    uint32_t a;
    asm("{ .reg .u64 t; cvta.to.shared.u64 t, %1; cvt.u32.u64 %0, t; }" : "=r"(a) : "l"(p));
    return a;
}
__device__ __forceinline__ void cp16(uint32_t dst, const void* src) {
    asm volatile("cp.async.cg.shared.global [%0], [%1], 16;" :: "r"(dst), "l"(src));
}
__device__ __forceinline__ void cp_commit() { asm volatile("cp.async.commit_group;"); }
__device__ __forceinline__ void cp_wait1()  { asm volatile("cp.async.wait_group 1;" ::: "memory"); }
__device__ __forceinline__ void cp_wait0()  { asm volatile("cp.async.wait_group 0;" ::: "memory"); }
__device__ __forceinline__ void ldsm_x4(uint32_t addr, uint32_t& r0, uint32_t& r1,
                                        uint32_t& r2, uint32_t& r3) {
    asm volatile("ldmatrix.sync.aligned.m8n8.x4.shared.b16 {%0,%1,%2,%3}, [%4];"
                 : "=r"(r0), "=r"(r1), "=r"(r2), "=r"(r3) : "r"(addr));
}
__device__ __forceinline__ void mma_bf16(float d[4], const uint32_t a[4], const uint32_t b[2]) {
    asm volatile(
        "mma.sync.aligned.m16n8k16.row.col.f32.bf16.bf16.f32 "
        "{%0,%1,%2,%3}, {%4,%5,%6,%7}, {%8,%9}, {%0,%1,%2,%3};"
        : "+f"(d[0]), "+f"(d[1]), "+f"(d[2]), "+f"(d[3])
        : "r"(a[0]), "r"(a[1]), "r"(a[2]), "r"(a[3]), "r"(b[0]), "r"(b[1]));
}

// ================= 0. assign: dedup marks + atomic slot assignment =================
// Slot order nondeterministic but every output bit is slot-independent.
__global__ void assign_kernel(const int* __restrict__ perm) {
    int k = blockIdx.x * blockDim.x + threadIdx.x;
    if (k >= Kneg) return;
    int p = perm[k];
#pragma unroll
    for (int t = 0; t < 2; t++) {
        int x = p + t;
        if (atomicExch(&g_mark[x], 1) == 0) {
            int s = atomicAdd(&g_Ucnt, 1);
            g_slot[x] = s;
            g_Ulist[s] = x;
        }
    }
}

// ================= 1. norms + positive logit =================
__global__ void norms_kernel(const float* __restrict__ zi, const float* __restrict__ zj) {
    int warp = (blockIdx.x * blockDim.x + threadIdx.x) >> 5;
    int lane = threadIdx.x & 31;
    if (warp >= Bsz) return;
    const float4* a = (const float4*)(zi + (size_t)warp * Ddim);
    const float4* b = (const float4*)(zj + (size_t)warp * Ddim);
    float si = 0.f, sj = 0.f, dij = 0.f;
#pragma unroll
    for (int c = 0; c < 4; c++) {
        float4 x = a[c * 32 + lane];
        float4 y = b[c * 32 + lane];
        si  += x.x*x.x + x.y*x.y + x.z*x.z + x.w*x.w;
        sj  += y.x*y.x + y.y*y.y + y.z*y.z + y.w*y.w;
        dij += x.x*y.x + x.y*y.y + x.z*y.z + x.w*y.w;
    }
#pragma unroll
    for (int o = 16; o > 0; o >>= 1) {
        si  += __shfl_down_sync(0xffffffffu, si, o);
        sj  += __shfl_down_sync(0xffffffffu, sj, o);
        dij += __shfl_down_sync(0xffffffffu, dij, o);
    }
    if (lane == 0) {
        float ni = sqrtf(si), nj = sqrtf(sj);
        g_ni[warp] = ni;
        g_nj[warp] = nj;
        g_plog[warp] = dij / fmaxf(ni * nj, EPSN) * 2.0f;
    }
}

// ================= 2. fused: split_zi + split_zj + maps =================
__device__ __forceinline__ void split8(const float* __restrict__ src,
                                       __nv_bfloat16* __restrict__ hi_out,
                                       __nv_bfloat16* __restrict__ lo_out) {
    float4 a = *(const float4*)(src);
    float4 b = *(const float4*)(src + 4);
    __nv_bfloat16 h[8], l[8];
    float v[8] = {a.x, a.y, a.z, a.w, b.x, b.y, b.z, b.w};
#pragma unroll
    for (int q = 0; q < 8; q++) {
        h[q] = __float2bfloat16(v[q]);
        l[q] = __float2bfloat16(v[q] - __bfloat162float(h[q]));
    }
    *(uint4*)hi_out = *(uint4*)h;
    *(uint4*)lo_out = *(uint4*)l;
}

#define ZI_BLOCKS  2048
#define ZJ_BLOCKS  1024
#define MAP_BLOCKS 8

__global__ void prep_kernel(const float* __restrict__ zi, const float* __restrict__ zj,
                            const int* __restrict__ perm) {
    int blk = blockIdx.x;
    int tid = threadIdx.x;
    if (blk < ZI_BLOCKS) {
        int idx = blk * 256 + tid;                 // Bsz*64
        size_t off = (size_t)idx * 8;
        split8(zi + off, g_Ahi + off, g_Alo + off);
    } else if (blk < ZI_BLOCKS + ZJ_BLOCKS) {
        int idx = (blk - ZI_BLOCKS) * 256 + tid;   // NPAD*64
        int u = idx >> 6;
        int g = idx & 63;
        int row = g_Ulist[u];
        size_t doff = (size_t)u * Ddim + g * 8;
        size_t soff = (size_t)row * Ddim + g * 8;
        split8(zj + soff, g_Bhi + doff, g_Blo + doff);
    } else {
        int k = (blk - ZI_BLOCKS - ZJ_BLOCKS) * 256 + tid;
        if (k < Kneg) {
            int p = perm[k];
            g_map0[k] = g_slot[p];
            g_map1[k] = g_slot[p + 1];
            g_nj0[k] = g_nj[p];
            g_nj1[k] = g_nj[p + 1];
        }
    }
}

// ================= 3. GEMM: bf16 m16n8k16, 3-term, term-major MMA ordering =================
#define ARRB  8192                  // 128 rows x 64B
#define STGB  (4 * ARRB)            // 32768 B
#define NSTG  3
#define SMEM_TOTAL (NSTG * STGB)    // 98304 B
#define NCHUNK (Ddim / 32)          // 16

// phys 16B-chunk: c ^ ((row>>1)&3)  -- conflict-free for ldmatrix reads and cp.async stores
__global__ __launch_bounds__(256, 2) void gemm_bf16_kernel() {
    const int n0 = blockIdx.x * 128;
    const int m0 = blockIdx.y * 128;
    if (n0 >= g_Ucnt) return;

    extern __shared__ char sm[];
    const uint32_t sb = smem_u32(sm);

    const int tid  = threadIdx.x;
    const int lane = tid & 31;
    const int wid  = tid >> 5;
    const int wm   = wid >> 1;        // 0..3
    const int wn   = wid & 1;         // 0..1

    // ---- cp.async assignment: arr = tid>>6; 8 x 16B per thread per stage-fill ----
    const int arr = tid >> 6;         // 0:Ahi 1:Alo 2:Bhi 3:Blo
    const int lt  = tid & 63;
    const __nv_bfloat16* garr =
        (arr == 0) ? g_Ahi + (size_t)m0 * Ddim :
        (arr == 1) ? g_Alo + (size_t)m0 * Ddim :
        (arr == 2) ? g_Bhi + (size_t)n0 * Ddim :
                     g_Blo + (size_t)n0 * Ddim;

    uint32_t st_dst[8];
    uint32_t st_src[8];
#pragma unroll
    for (int q = 0; q < 8; q++) {
        int row = lt + 64 * (q >> 2);
        int c   = q & 3;
        int phys = c ^ ((row >> 1) & 3);
        st_dst[q] = (uint32_t)(arr * ARRB + row * 64 + phys * 16);
        st_src[q] = (uint32_t)(row * Ddim + c * 8);     // element offset
    }

    // per-lane ldmatrix offsets (g=0; g=1 is ^32)
    uint32_t aoff[2];
#pragma unroll
    for (int mt = 0; mt < 2; mt++) {
        int row = wm * 32 + mt * 16 + (lane & 15);
        int ch  = (lane >> 4);
        int phys = ch ^ ((row >> 1) & 3);
        aoff[mt] = (uint32_t)(row * 64 + phys * 16);
    }
    uint32_t boff[4];
#pragma unroll
    for (int p = 0; p < 4; p++) {
        int row = wn * 64 + p * 16 + (((lane >> 4) & 1) << 3) + (lane & 7);
        int ch  = (lane >> 3) & 1;
        int phys = ch ^ ((row >> 1) & 3);
        boff[p] = (uint32_t)(2 * ARRB + row * 64 + phys * 16);
    }

    float d[2][8][4];
#pragma unroll
    for (int mt = 0; mt < 2; mt++)
#pragma unroll
        for (int nt = 0; nt < 8; nt++)
#pragma unroll
            for (int q = 0; q < 4; q++) d[mt][nt][q] = 0.f;

    // prologue: chunks 0 and 1
#pragma unroll
    for (int ck = 0; ck < 2; ck++) {
        uint32_t stg = sb + ck * STGB;
#pragma unroll
        for (int q = 0; q < 8; q++)
            cp16(stg + st_dst[q], garr + ck * 32 + st_src[q]);
        cp_commit();
    }

    for (int c = 0; c < NCHUNK; c++) {
        if (c + 1 < NCHUNK) cp_wait1(); else cp_wait0();
        __syncthreads();

        // issue chunk c+2 into stage (c+2)%3
        if (c + 2 < NCHUNK) {
            uint32_t stg = sb + ((c + 2) % NSTG) * STGB;
            const __nv_bfloat16* gsrc = garr + (c + 2) * 32;
#pragma unroll
            for (int q = 0; q < 8; q++)
                cp16(stg + st_dst[q], gsrc + st_src[q]);
            cp_commit();
        }

        const uint32_t s0 = sb + (c % NSTG) * STGB;
#pragma unroll
        for (int g = 0; g < 2; g++) {
            const uint32_t gx = (uint32_t)(g * 32);   // +k16 == ^32 on phys chunk
            // ---- load ALL fragments for this k16 group (12 x ldmatrix.x4) ----
            uint32_t ah[2][4], al[2][4], bh[4][4], bl[4][4];
#pragma unroll
            for (int mt = 0; mt < 2; mt++) {
                uint32_t ra = s0 + (aoff[mt] ^ gx);
                ldsm_x4(ra,        ah[mt][0], ah[mt][1], ah[mt][2], ah[mt][3]);
                ldsm_x4(ra + ARRB, al[mt][0], al[mt][1], al[mt][2], al[mt][3]);
            }
#pragma unroll
            for (int p = 0; p < 4; p++) {
                uint32_t rb = s0 + (boff[p] ^ gx);
                ldsm_x4(rb,        bh[p][0], bh[p][1], bh[p][2], bh[p][3]);
                ldsm_x4(rb + ARRB, bl[p][0], bl[p][1], bl[p][2], bl[p][3]);
            }
            // ---- term-major: 16 independent MMAs per pass, acc reuse gap = 16 ----
#pragma unroll
            for (int mt = 0; mt < 2; mt++)              // pass 1: HH
#pragma unroll
                for (int p = 0; p < 4; p++)
#pragma unroll
                    for (int j = 0; j < 2; j++)
                        mma_bf16(d[mt][p * 2 + j], ah[mt], bh[p] + j * 2);
#pragma unroll
            for (int mt = 0; mt < 2; mt++)              // pass 2: HL
#pragma unroll
                for (int p = 0; p < 4; p++)
#pragma unroll
                    for (int j = 0; j < 2; j++)
                        mma_bf16(d[mt][p * 2 + j], ah[mt], bl[p] + j * 2);
#pragma unroll
            for (int mt = 0; mt < 2; mt++)              // pass 3: LH
#pragma unroll
                for (int p = 0; p < 4; p++)
#pragma unroll
                    for (int j = 0; j < 2; j++)
                        mma_bf16(d[mt][p * 2 + j], al[mt], bh[p] + j * 2);
        }
    }

    // ---- epilogue ----
#pragma unroll
    for (int mt = 0; mt < 2; mt++) {
        int r0 = m0 + wm * 32 + mt * 16 + (lane >> 2);
#pragma unroll
        for (int nt = 0; nt < 8; nt++) {
            int col = n0 + wn * 64 + nt * 8 + (lane & 3) * 2;
            float* p0 = g_C + (size_t)r0 * NPAD + col;
            float* p1 = g_C + (size_t)(r0 + 8) * NPAD + col;
            *(float2*)p0 = make_float2(d[mt][nt][0], d[mt][nt][1]);
            *(float2*)p1 = make_float2(d[mt][nt][2], d[mt][nt][3]);
        }
    }
}

// ================= 4. per-row logsumexp + rank counts =================
__global__ __launch_bounds__(256) void reduce_kernel(const int* __restrict__ perm) {
    __shared__ int   s_p[Kneg];
    __shared__ int   s_m0[Kneg];
    __shared__ int   s_m1[Kneg];
    __shared__ float s_n0[Kneg];
    __shared__ float s_n1[Kneg];
    __shared__ float redf[256];
    __shared__ int   redi[256];

    int tid = threadIdx.x;
    for (int k = tid; k < Kneg; k += 256) {
        s_p[k]  = perm[k];
        s_m0[k] = g_map0[k];
        s_m1[k] = g_map1[k];
        s_n0[k] = g_nj0[k];
        s_n1[k] = g_nj1[k];
    }
    __syncthreads();

    for (int r = 0; r < 8; r++) {
        int i = blockIdx.x * 8 + r;
        float ni = g_ni[i];
        float lp = g_plog[i];
        const float* Crow = g_C + (size_t)i * NPAD;

        float tmax = lp;
        for (int k = tid; k < Kneg; k += 256) {
            bool sel = (s_p[k] >= i);
            int slot  = sel ? s_m1[k] : s_m0[k];
            float njc = sel ? s_n1[k] : s_n0[k];
            float l = Crow[slot] / fmaxf(ni * njc, EPSN) * 2.0f;
            tmax = fmaxf(tmax, l);
        }
        redf[tid] = tmax;
        __syncthreads();
        for (int o = 128; o > 0; o >>= 1) {
            if (tid < o) redf[tid] = fmaxf(redf[tid], redf[tid + o]);
            __syncthreads();
        }
        float M = redf[0];
        __syncthreads();

        float s = 0.f;
        int cnt = 0;
        for (int k = tid; k < Kneg; k += 256) {
            bool sel = (s_p[k] >= i);
            int slot  = sel ? s_m1[k] : s_m0[k];
            float njc = sel ? s_n1[k] : s_n0[k];
            float l = Crow[slot] / fmaxf(ni * njc, EPSN) * 2.0f;
            s += expf(l - M);
            cnt += (l > lp) ? 1 : 0;
        }
        redf[tid] = s;
        redi[tid] = cnt;
        __syncthreads();
        for (int o = 128; o > 0; o >>= 1) {
            if (tid < o) { redf[tid] += redf[tid + o]; redi[tid] += redi[tid + o]; }
            __syncthreads();
        }
        if (tid == 0) {
            g_loss[i] = M + logf(redf[0] + expf(lp - M)) - lp;
            g_cnt[i]  = redi[0];
        }
        __syncthreads();
    }
}

// ================= 5. final reduction + state cleanup =================
__global__ void final_kernel(float* __restrict__ out) {
    __shared__ float sf[1024];
    __shared__ int   s1[1024];
    __shared__ int   s5[1024];
    int tid = threadIdx.x;
    float s = 0.f;
    int c1 = 0, c5 = 0;
    for (int i = tid; i < Bsz; i += 1024) {
        s += g_loss[i];
        int c = g_cnt[i];
        c1 += (c == 0) ? 1 : 0;
        c5 += (c <= 4) ? 1 : 0;
    }
    sf[tid] = s; s1[tid] = c1; s5[tid] = c5;
    __syncthreads();
    for (int o = 512; o > 0; o >>= 1) {
        if (tid < o) { sf[tid] += sf[tid + o]; s1[tid] += s1[tid + o]; s5[tid] += s5[tid + o]; }
        __syncthreads();
    }
    if (tid == 0) {
        out[0] = sf[0] / (float)Bsz;
        out[1] = 100.0f * (float)s1[0] / (float)Bsz;
        out[2] = 100.0f * (float)s5[0] / (float)Bsz;
        g_Ucnt = 0;                               // self-clean for next replay
    }
    for (int i = tid; i < Bsz; i += 1024) g_mark[i] = 0;
}

// ================= launch =================
extern "C" void kernel_launch(void* const* d_in, const int* in_sizes, int n_in,
                              void* d_out, int out_size) {
    const float* zi   = (const float*)d_in[0];
    const float* zj   = (const float*)d_in[1];
    const int*   perm = (const int*)d_in[2];
    float* out = (float*)d_out;

    cudaFuncSetAttribute(gemm_bf16_kernel, cudaFuncAttributeMaxDynamicSharedMemorySize, SMEM_TOTAL);

    assign_kernel<<<2, 1024>>>(perm);                                // 0
    norms_kernel<<<Bsz / 8, 256>>>(zi, zj);                          // 1
    prep_kernel<<<ZI_BLOCKS + ZJ_BLOCKS + MAP_BLOCKS, 256>>>(zi, zj, perm); // 2
    dim3 g(NPAD / 128, Bsz / 128);                                   // 32 x 64
    gemm_bf16_kernel<<<g, 256, SMEM_TOTAL>>>();                      // 3  (ncu target)
    reduce_kernel<<<Bsz / 8, 256>>>(perm);                           // 4
    final_kernel<<<1, 1024>>>(out);                                  // 5
}

// round 14
// speedup vs baseline: 2.3074x; 1.3577x over previous
#include <cuda_runtime.h>
#include <cuda_bf16.h>
#include <math.h>
#include <stdint.h>

#define Bsz   8192
#define Ddim  512
#define Kneg  2048
#define NPAD  4096
#define EPSN  1e-8f

// ================= scratch =================
__device__ float        g_C[(size_t)Bsz * NPAD];
__device__ __nv_bfloat16 g_Ahi[(size_t)Bsz * Ddim];
__device__ __nv_bfloat16 g_Alo[(size_t)Bsz * Ddim];
__device__ __nv_bfloat16 g_Bhi[(size_t)NPAD * Ddim];
__device__ __nv_bfloat16 g_Blo[(size_t)NPAD * Ddim];
__device__ float g_ni[Bsz], g_nj[Bsz], g_plog[Bsz];
__device__ int   g_mark[Bsz], g_slot[Bsz];
__device__ int   g_Ulist[NPAD];           // zero-init; pad slots stay 0 forever
__device__ int   g_map0[Kneg], g_map1[Kneg];
__device__ float g_nj0[Kneg], g_nj1[Kneg];
__device__ int   g_Ucnt;                  // reset by final_kernel each replay
__device__ float g_loss[Bsz];
__device__ int   g_cnt[Bsz];

// ================= PTX helpers =================
__device__ __forceinline__ uint32_t smem_u32(const void* p) {
    uint32_t a;
    asm("{ .reg .u64 t; cvta.to.shared.u64 t, %1; cvt.u32.u64 %0, t; }" : "=r"(a) : "l"(p));
    return a;
}
__device__ __forceinline__ void cp16(uint32_t dst, const void* src) {
    asm volatile("cp.async.cg.shared.global [%0], [%1], 16;" :: "r"(dst), "l"(src));
}
__device__ __forceinline__ void cp_commit() { asm volatile("cp.async.commit_group;"); }
__device__ __forceinline__ void cp_wait1()  { asm volatile("cp.async.wait_group 1;" ::: "memory"); }
__device__ __forceinline__ void cp_wait0()  { asm volatile("cp.async.wait_group 0;" ::: "memory"); }
__device__ __forceinline__ void ldsm_x4(uint32_t addr, uint32_t& r0, uint32_t& r1,
                                        uint32_t& r2, uint32_t& r3) {
    asm volatile("ldmatrix.sync.aligned.m8n8.x4.shared.b16 {%0,%1,%2,%3}, [%4];"
                 : "=r"(r0), "=r"(r1), "=r"(r2), "=r"(r3) : "r"(addr));
}
__device__ __forceinline__ void mma_bf16(float d[4], const uint32_t a[4], const uint32_t b[2]) {
    asm volatile(
        "mma.sync.aligned.m16n8k16.row.col.f32.bf16.bf16.f32 "
        "{%0,%1,%2,%3}, {%4,%5,%6,%7}, {%8,%9}, {%0,%1,%2,%3};"
        : "+f"(d[0]), "+f"(d[1]), "+f"(d[2]), "+f"(d[3])
        : "r"(a[0]), "r"(a[1]), "r"(a[2]), "r"(a[3]), "r"(b[0]), "r"(b[1]));
}

// ================= 0. assign: dedup marks + atomic slot assignment =================
// Slot order nondeterministic but every output bit is slot-independent.
__global__ void assign_kernel(const int* __restrict__ perm) {
    int k = blockIdx.x * blockDim.x + threadIdx.x;
    if (k >= Kneg) return;
    int p = perm[k];
#pragma unroll
    for (int t = 0; t < 2; t++) {
        int x = p + t;
        if (atomicExch(&g_mark[x], 1) == 0) {
            int s = atomicAdd(&g_Ucnt, 1);
            g_slot[x] = s;
            g_Ulist[s] = x;
        }
    }
}

// ================= 1. norms + positive logit =================
__global__ void norms_kernel(const float* __restrict__ zi, const float* __restrict__ zj) {
    int warp = (blockIdx.x * blockDim.x + threadIdx.x) >> 5;
    int lane = threadIdx.x & 31;
    if (warp >= Bsz) return;
    const float4* a = (const float4*)(zi + (size_t)warp * Ddim);
    const float4* b = (const float4*)(zj + (size_t)warp * Ddim);
    float si = 0.f, sj = 0.f, dij = 0.f;
#pragma unroll
    for (int c = 0; c < 4; c++) {
        float4 x = a[c * 32 + lane];
        float4 y = b[c * 32 + lane];
        si  += x.x*x.x + x.y*x.y + x.z*x.z + x.w*x.w;
        sj  += y.x*y.x + y.y*y.y + y.z*y.z + y.w*y.w;
        dij += x.x*y.x + x.y*y.y + x.z*y.z + x.w*y.w;
    }
#pragma unroll
    for (int o = 16; o > 0; o >>= 1) {
        si  += __shfl_down_sync(0xffffffffu, si, o);
        sj  += __shfl_down_sync(0xffffffffu, sj, o);
        dij += __shfl_down_sync(0xffffffffu, dij, o);
    }
    if (lane == 0) {
        float ni = sqrtf(si), nj = sqrtf(sj);
        g_ni[warp] = ni;
        g_nj[warp] = nj;
        g_plog[warp] = dij / fmaxf(ni * nj, EPSN) * 2.0f;
    }
}

// ================= 2. fused: split_zi + split_zj + maps =================
__device__ __forceinline__ void split8(const float* __restrict__ src,
                                       __nv_bfloat16* __restrict__ hi_out,
                                       __nv_bfloat16* __restrict__ lo_out) {
    float4 a = *(const float4*)(src);
    float4 b = *(const float4*)(src + 4);
    __nv_bfloat16 h[8], l[8];
    float v[8] = {a.x, a.y, a.z, a.w, b.x, b.y, b.z, b.w};
#pragma unroll
    for (int q = 0; q < 8; q++) {
        h[q] = __float2bfloat16(v[q]);
        l[q] = __float2bfloat16(v[q] - __bfloat162float(h[q]));
    }
    *(uint4*)hi_out = *(uint4*)h;
    *(uint4*)lo_out = *(uint4*)l;
}

#define ZI_BLOCKS  2048
#define ZJ_BLOCKS  1024
#define MAP_BLOCKS 8

__global__ void prep_kernel(const float* __restrict__ zi, const float* __restrict__ zj,
                            const int* __restrict__ perm) {
    int blk = blockIdx.x;
    int tid = threadIdx.x;
    if (blk < ZI_BLOCKS) {
        int idx = blk * 256 + tid;                 // Bsz*64
        size_t off = (size_t)idx * 8;
        split8(zi + off, g_Ahi + off, g_Alo + off);
    } else if (blk < ZI_BLOCKS + ZJ_BLOCKS) {
        int idx = (blk - ZI_BLOCKS) * 256 + tid;   // NPAD*64
        int u = idx >> 6;
        int g = idx & 63;
        int row = g_Ulist[u];
        size_t doff = (size_t)u * Ddim + g * 8;
        size_t soff = (size_t)row * Ddim + g * 8;
        split8(zj + soff, g_Bhi + doff, g_Blo + doff);
    } else {
        int k = (blk - ZI_BLOCKS - ZJ_BLOCKS) * 256 + tid;
        if (k < Kneg) {
            int p = perm[k];
            g_map0[k] = g_slot[p];
            g_map1[k] = g_slot[p + 1];
            g_nj0[k] = g_nj[p];
            g_nj1[k] = g_nj[p + 1];
        }
    }
}

// ================= 3. GEMM: bf16 m16n8k16, 3-term, 128x64 tile, 3 CTAs/SM =================
// CTA tile 128(M) x 64(N), 256 threads (8 warps), warp tile 32x32.
// K chunks of 32 f32 (64B rows), 3-stage cp.async distance-2, XOR 16B-chunk swizzle.
#define A_HI  0
#define A_LO  8192
#define B_HI  16384
#define B_LO  20480
#define STGB  24576                 // 24 KB per stage
#define NSTG  3
#define SMEM_TOTAL (NSTG * STGB)    // 73728 B -> 3 CTAs/SM (216 KB of 228)
#define NCHUNK (Ddim / 32)          // 16

__global__ __launch_bounds__(256, 3) void gemm_bf16_kernel() {
    const int n0 = blockIdx.x * 64;
    const int m0 = blockIdx.y * 128;
    if (n0 >= g_Ucnt) return;

    extern __shared__ char sm[];
    const uint32_t sb = smem_u32(sm);

    const int tid  = threadIdx.x;
    const int lane = tid & 31;
    const int wid  = tid >> 5;
    const int wm   = wid >> 1;        // 0..3 (32-row slice)
    const int wn   = wid & 1;         // 0..1 (32-col slice)

    const __nv_bfloat16* pAhi = g_Ahi + (size_t)m0 * Ddim;
    const __nv_bfloat16* pAlo = g_Alo + (size_t)m0 * Ddim;
    const __nv_bfloat16* pBhi = g_Bhi + (size_t)n0 * Ddim;
    const __nv_bfloat16* pBlo = g_Blo + (size_t)n0 * Ddim;

    // per-lane ldmatrix offsets (group g=0; g=1 is ^32 on the address)
    uint32_t aoff[2];
#pragma unroll
    for (int mt = 0; mt < 2; mt++) {
        int row = wm * 32 + mt * 16 + (lane & 15);
        int phys = (lane >> 4) ^ ((row >> 1) & 3);
        aoff[mt] = (uint32_t)(A_HI + row * 64 + phys * 16);
    }
    uint32_t boff[2];
#pragma unroll
    for (int p = 0; p < 2; p++) {
        int row = wn * 32 + p * 16 + (((lane >> 4) & 1) << 3) + (lane & 7);
        int phys = ((lane >> 3) & 1) ^ ((row >> 1) & 3);
        boff[p] = (uint32_t)(B_HI + row * 64 + phys * 16);
    }

    float d[2][4][4];
#pragma unroll
    for (int mt = 0; mt < 2; mt++)
#pragma unroll
        for (int nt = 0; nt < 4; nt++)
#pragma unroll
            for (int q = 0; q < 4; q++) d[mt][nt][q] = 0.f;

    // stage fill: 1536 cp16 / 256 threads = 6 per thread
    //   t=0,1 -> Ahi ; t=2,3 -> Alo ; t=4 -> Bhi ; t=5 -> Blo
#define FILL_STAGE(stg_base, koff)                                              \
    {                                                                           \
        _Pragma("unroll")                                                       \
        for (int t = 0; t < 6; t++) {                                           \
            int local; uint32_t abase; const __nv_bfloat16* gbase;              \
            if (t < 2)      { local = tid + t * 256;       abase = A_HI; gbase = pAhi; } \
            else if (t < 4) { local = tid + (t - 2) * 256; abase = A_LO; gbase = pAlo; } \
            else if (t == 4){ local = tid;                 abase = B_HI; gbase = pBhi; } \
            else            { local = tid;                 abase = B_LO; gbase = pBlo; } \
            int row  = local >> 2;                                              \
            int ch   = local & 3;                                               \
            int phys = ch ^ ((row >> 1) & 3);                                   \
            cp16((stg_base) + abase + (uint32_t)(row * 64 + phys * 16),         \
                 gbase + (size_t)row * Ddim + ch * 8 + (koff));                 \
        }                                                                       \
    }

    // prologue: chunks 0 and 1
#pragma unroll
    for (int ck = 0; ck < 2; ck++) {
        uint32_t stg = sb + ck * STGB;
        FILL_STAGE(stg, ck * 32);
        cp_commit();
    }

    for (int c = 0; c < NCHUNK; c++) {
        if (c + 1 < NCHUNK) cp_wait1(); else cp_wait0();
        __syncthreads();

        // issue chunk c+2 into stage (c+2)%3
        if (c + 2 < NCHUNK) {
            uint32_t stg = sb + ((c + 2) % NSTG) * STGB;
            FILL_STAGE(stg, (c + 2) * 32);
            cp_commit();
        }

        const uint32_t s0 = sb + (c % NSTG) * STGB;
#pragma unroll
        for (int g = 0; g < 2; g++) {
            const uint32_t gx = (uint32_t)(g * 32);   // +k16 == ^32 on phys chunk
            uint32_t ah[2][4], al[2][4], bh[2][4], bl[2][4];
#pragma unroll
            for (int mt = 0; mt < 2; mt++) {
                uint32_t ra = s0 + (aoff[mt] ^ gx);
                ldsm_x4(ra,            ah[mt][0], ah[mt][1], ah[mt][2], ah[mt][3]);
                ldsm_x4(ra + 8192,     al[mt][0], al[mt][1], al[mt][2], al[mt][3]);
            }
#pragma unroll
            for (int p = 0; p < 2; p++) {
                uint32_t rb = s0 + (boff[p] ^ gx);
                ldsm_x4(rb,            bh[p][0], bh[p][1], bh[p][2], bh[p][3]);
                ldsm_x4(rb + 4096,     bl[p][0], bl[p][1], bl[p][2], bl[p][3]);
            }
            // term-major passes (HH, HL, LH) -- same accumulation order as before
#pragma unroll
            for (int mt = 0; mt < 2; mt++)
#pragma unroll
                for (int p = 0; p < 2; p++)
#pragma unroll
                    for (int j = 0; j < 2; j++)
                        mma_bf16(d[mt][p * 2 + j], ah[mt], bh[p] + j * 2);
#pragma unroll
            for (int mt = 0; mt < 2; mt++)
#pragma unroll
                for (int p = 0; p < 2; p++)
#pragma unroll
                    for (int j = 0; j < 2; j++)
                        mma_bf16(d[mt][p * 2 + j], ah[mt], bl[p] + j * 2);
#pragma unroll
            for (int mt = 0; mt < 2; mt++)
#pragma unroll
                for (int p = 0; p < 2; p++)
#pragma unroll
                    for (int j = 0; j < 2; j++)
                        mma_bf16(d[mt][p * 2 + j], al[mt], bh[p] + j * 2);
        }
    }

    // ---- epilogue ----
#pragma unroll
    for (int mt = 0; mt < 2; mt++) {
        int r0 = m0 + wm * 32 + mt * 16 + (lane >> 2);
#pragma unroll
        for (int nt = 0; nt < 4; nt++) {
            int col = n0 + wn * 32 + nt * 8 + (lane & 3) * 2;
            float* p0 = g_C + (size_t)r0 * NPAD + col;
            float* p1 = g_C + (size_t)(r0 + 8) * NPAD + col;
            *(float2*)p0 = make_float2(d[mt][nt][0], d[mt][nt][1]);
            *(float2*)p1 = make_float2(d[mt][nt][2], d[mt][nt][3]);
        }
    }
}

// ================= 4. per-row logsumexp + rank counts =================
__global__ __launch_bounds__(256) void reduce_kernel(const int* __restrict__ perm) {
    __shared__ int   s_p[Kneg];
    __shared__ int   s_m0[Kneg];
    __shared__ int   s_m1[Kneg];
    __shared__ float s_n0[Kneg];
    __shared__ float s_n1[Kneg];
    __shared__ float redf[256];
    __shared__ int   redi[256];

    int tid = threadIdx.x;
    for (int k = tid; k < Kneg; k += 256) {
        s_p[k]  = perm[k];
        s_m0[k] = g_map0[k];
        s_m1[k] = g_map1[k];
        s_n0[k] = g_nj0[k];
        s_n1[k] = g_nj1[k];
    }
    __syncthreads();

    for (int r = 0; r < 8; r++) {
        int i = blockIdx.x * 8 + r;
        float ni = g_ni[i];
        float lp = g_plog[i];
        const float* Crow = g_C + (size_t)i * NPAD;

        float tmax = lp;
        for (int k = tid; k < Kneg; k += 256) {
            bool sel = (s_p[k] >= i);
            int slot  = sel ? s_m1[k] : s_m0[k];
            float njc = sel ? s_n1[k] : s_n0[k];
            float l = Crow[slot] / fmaxf(ni * njc, EPSN) * 2.0f;
            tmax = fmaxf(tmax, l);
        }
        redf[tid] = tmax;
        __syncthreads();
        for (int o = 128; o > 0; o >>= 1) {
            if (tid < o) redf[tid] = fmaxf(redf[tid], redf[tid + o]);
            __syncthreads();
        }
        float M = redf[0];
        __syncthreads();

        float s = 0.f;
        int cnt = 0;
        for (int k = tid; k < Kneg; k += 256) {
            bool sel = (s_p[k] >= i);
            int slot  = sel ? s_m1[k] : s_m0[k];
            float njc = sel ? s_n1[k] : s_n0[k];
            float l = Crow[slot] / fmaxf(ni * njc, EPSN) * 2.0f;
            s += expf(l - M);
            cnt += (l > lp) ? 1 : 0;
        }
        redf[tid] = s;
        redi[tid] = cnt;
        __syncthreads();
        for (int o = 128; o > 0; o >>= 1) {
            if (tid < o) { redf[tid] += redf[tid + o]; redi[tid] += redi[tid + o]; }
            __syncthreads();
        }
        if (tid == 0) {
            g_loss[i] = M + logf(redf[0] + expf(lp - M)) - lp;
            g_cnt[i]  = redi[0];
        }
        __syncthreads();
    }
}

// ================= 5. final reduction + state cleanup =================
__global__ void final_kernel(float* __restrict__ out) {
    __shared__ float sf[1024];
    __shared__ int   s1[1024];
    __shared__ int   s5[1024];
    int tid = threadIdx.x;
    float s = 0.f;
    int c1 = 0, c5 = 0;
    for (int i = tid; i < Bsz; i += 1024) {
        s += g_loss[i];
        int c = g_cnt[i];
        c1 += (c == 0) ? 1 : 0;
        c5 += (c <= 4) ? 1 : 0;
    }
    sf[tid] = s; s1[tid] = c1; s5[tid] = c5;
    __syncthreads();
    for (int o = 512; o > 0; o >>= 1) {
        if (tid < o) { sf[tid] += sf[tid + o]; s1[tid] += s1[tid + o]; s5[tid] += s5[tid + o]; }
        __syncthreads();
    }
    if (tid == 0) {
        out[0] = sf[0] / (float)Bsz;
        out[1] = 100.0f * (float)s1[0] / (float)Bsz;
        out[2] = 100.0f * (float)s5[0] / (float)Bsz;
        g_Ucnt = 0;                               // self-clean for next replay
    }
    for (int i = tid; i < Bsz; i += 1024) g_mark[i] = 0;
}

// ================= launch =================
extern "C" void kernel_launch(void* const* d_in, const int* in_sizes, int n_in,
                              void* d_out, int out_size) {
    const float* zi   = (const float*)d_in[0];
    const float* zj   = (const float*)d_in[1];
    const int*   perm = (const int*)d_in[2];
    float* out = (float*)d_out;

    cudaFuncSetAttribute(gemm_bf16_kernel, cudaFuncAttributeMaxDynamicSharedMemorySize, SMEM_TOTAL);

    assign_kernel<<<2, 1024>>>(perm);                                // 0
    norms_kernel<<<Bsz / 8, 256>>>(zi, zj);                          // 1
    prep_kernel<<<ZI_BLOCKS + ZJ_BLOCKS + MAP_BLOCKS, 256>>>(zi, zj, perm); // 2
    dim3 g(NPAD / 64, Bsz / 128);                                    // 64 x 64
    gemm_bf16_kernel<<<g, 256, SMEM_TOTAL>>>();                      // 3  (ncu target)
    reduce_kernel<<<Bsz / 8, 256>>>(perm);                           // 4
    final_kernel<<<1, 1024>>>(out);                                  // 5
}

// round 17
// speedup vs baseline: 2.7373x; 1.1863x over previous
#include <cuda_runtime.h>
#include <cuda_bf16.h>
#include <math.h>
#include <stdint.h>

#define Bsz   8192
#define Ddim  512
#define Kneg  2048
#define NPAD  4096
#define EPSN  1e-8f

// ================= scratch =================
__device__ float        g_C[(size_t)Bsz * NPAD];
__device__ __nv_bfloat16 g_Ahi[(size_t)Bsz * Ddim];
__device__ __nv_bfloat16 g_Alo[(size_t)Bsz * Ddim];
__device__ __nv_bfloat16 g_Bhi[(size_t)NPAD * Ddim];
__device__ __nv_bfloat16 g_Blo[(size_t)NPAD * Ddim];
__device__ float g_ni[Bsz], g_nj[Bsz], g_plog[Bsz];
__device__ int   g_mark[Bsz], g_slot[Bsz];
__device__ int   g_Ulist[NPAD];           // zero-init; pad slots stay 0 forever
__device__ int   g_map0[Kneg], g_map1[Kneg];
__device__ float g_nj0[Kneg], g_nj1[Kneg];
__device__ int   g_Ucnt;                  // reset by final_kernel each replay
__device__ float g_loss[Bsz];
__device__ int   g_cnt[Bsz];

// ================= PTX helpers =================
__device__ __forceinline__ uint32_t smem_u32(const void* p) {
    uint32_t a;
    asm("{ .reg .u64 t; cvta.to.shared.u64 t, %1; cvt.u32.u64 %0, t; }" : "=r"(a) : "l"(p));
    return a;
}
__device__ __forceinline__ void cp16(uint32_t dst, const void* src) {
    asm volatile("cp.async.cg.shared.global [%0], [%1], 16;" :: "r"(dst), "l"(src));
}
__device__ __forceinline__ void cp_commit() { asm volatile("cp.async.commit_group;"); }
__device__ __forceinline__ void cp_wait1()  { asm volatile("cp.async.wait_group 1;" ::: "memory"); }
__device__ __forceinline__ void cp_wait0()  { asm volatile("cp.async.wait_group 0;" ::: "memory"); }
__device__ __forceinline__ void ldsm_x4(uint32_t addr, uint32_t& r0, uint32_t& r1,
                                        uint32_t& r2, uint32_t& r3) {
    asm volatile("ldmatrix.sync.aligned.m8n8.x4.shared.b16 {%0,%1,%2,%3}, [%4];"
                 : "=r"(r0), "=r"(r1), "=r"(r2), "=r"(r3) : "r"(addr));
}
__device__ __forceinline__ void mma_bf16(float d[4], const uint32_t a[4], const uint32_t b[2]) {
    asm volatile(
        "mma.sync.aligned.m16n8k16.row.col.f32.bf16.bf16.f32 "
        "{%0,%1,%2,%3}, {%4,%5,%6,%7}, {%8,%9}, {%0,%1,%2,%3};"
        : "+f"(d[0]), "+f"(d[1]), "+f"(d[2]), "+f"(d[3])
        : "r"(a[0]), "r"(a[1]), "r"(a[2]), "r"(a[3]), "r"(b[0]), "r"(b[1]));
}

// ================= 0. assign: dedup marks + atomic slot assignment =================
// Slot order nondeterministic but every output bit is slot-independent.
__global__ void assign_kernel(const int* __restrict__ perm) {
    int k = blockIdx.x * blockDim.x + threadIdx.x;
    if (k >= Kneg) return;
    int p = perm[k];
#pragma unroll
    for (int t = 0; t < 2; t++) {
        int x = p + t;
        if (atomicExch(&g_mark[x], 1) == 0) {
            int s = atomicAdd(&g_Ucnt, 1);
            g_slot[x] = s;
            g_Ulist[s] = x;
        }
    }
}

// ================= 1. norms + positive logit =================
__global__ void norms_kernel(const float* __restrict__ zi, const float* __restrict__ zj) {
    int warp = (blockIdx.x * blockDim.x + threadIdx.x) >> 5;
    int lane = threadIdx.x & 31;
    if (warp >= Bsz) return;
    const float4* a = (const float4*)(zi + (size_t)warp * Ddim);
    const float4* b = (const float4*)(zj + (size_t)warp * Ddim);
    float si = 0.f, sj = 0.f, dij = 0.f;
#pragma unroll
    for (int c = 0; c < 4; c++) {
        float4 x = a[c * 32 + lane];
        float4 y = b[c * 32 + lane];
        si  += x.x*x.x + x.y*x.y + x.z*x.z + x.w*x.w;
        sj  += y.x*y.x + y.y*y.y + y.z*y.z + y.w*y.w;
        dij += x.x*y.x + x.y*y.y + x.z*y.z + x.w*y.w;
    }
#pragma unroll
    for (int o = 16; o > 0; o >>= 1) {
        si  += __shfl_down_sync(0xffffffffu, si, o);
        sj  += __shfl_down_sync(0xffffffffu, sj, o);
        dij += __shfl_down_sync(0xffffffffu, dij, o);
    }
    if (lane == 0) {
        float ni = sqrtf(si), nj = sqrtf(sj);
        g_ni[warp] = ni;
        g_nj[warp] = nj;
        g_plog[warp] = dij / fmaxf(ni * nj, EPSN) * 2.0f;
    }
}

// ================= 2. fused: split_zi + split_zj + maps =================
__device__ __forceinline__ void split8(const float* __restrict__ src,
                                       __nv_bfloat16* __restrict__ hi_out,
                                       __nv_bfloat16* __restrict__ lo_out) {
    float4 a = *(const float4*)(src);
    float4 b = *(const float4*)(src + 4);
    __nv_bfloat16 h[8], l[8];
    float v[8] = {a.x, a.y, a.z, a.w, b.x, b.y, b.z, b.w};
#pragma unroll
    for (int q = 0; q < 8; q++) {
        h[q] = __float2bfloat16(v[q]);
        l[q] = __float2bfloat16(v[q] - __bfloat162float(h[q]));
    }
    *(uint4*)hi_out = *(uint4*)h;
    *(uint4*)lo_out = *(uint4*)l;
}

#define ZI_BLOCKS  2048
#define ZJ_BLOCKS  1024
#define MAP_BLOCKS 8

__global__ void prep_kernel(const float* __restrict__ zi, const float* __restrict__ zj,
                            const int* __restrict__ perm) {
    int blk = blockIdx.x;
    int tid = threadIdx.x;
    if (blk < ZI_BLOCKS) {
        int idx = blk * 256 + tid;                 // Bsz*64
        size_t off = (size_t)idx * 8;
        split8(zi + off, g_Ahi + off, g_Alo + off);
    } else if (blk < ZI_BLOCKS + ZJ_BLOCKS) {
        int idx = (blk - ZI_BLOCKS) * 256 + tid;   // NPAD*64
        int u = idx >> 6;
        int g = idx & 63;
        int row = g_Ulist[u];
        size_t doff = (size_t)u * Ddim + g * 8;
        size_t soff = (size_t)row * Ddim + g * 8;
        split8(zj + soff, g_Bhi + doff, g_Blo + doff);
    } else {
        int k = (blk - ZI_BLOCKS - ZJ_BLOCKS) * 256 + tid;
        if (k < Kneg) {
            int p = perm[k];
            g_map0[k] = g_slot[p];
            g_map1[k] = g_slot[p + 1];
            g_nj0[k] = g_nj[p];
            g_nj1[k] = g_nj[p + 1];
        }
    }
}

// ================= 3. GEMM: bf16 m16n8k16, 3-term, 128x64 tile, 3 CTAs/SM =================
// (unchanged from round 14)
#define A_HI  0
#define A_LO  8192
#define B_HI  16384
#define B_LO  20480
#define STGB  24576                 // 24 KB per stage
#define NSTG  3
#define SMEM_TOTAL (NSTG * STGB)    // 73728 B -> 3 CTAs/SM (216 KB of 228)
#define NCHUNK (Ddim / 32)          // 16

__global__ __launch_bounds__(256, 3) void gemm_bf16_kernel() {
    const int n0 = blockIdx.x * 64;
    const int m0 = blockIdx.y * 128;
    if (n0 >= g_Ucnt) return;

    extern __shared__ char sm[];
    const uint32_t sb = smem_u32(sm);

    const int tid  = threadIdx.x;
    const int lane = tid & 31;
    const int wid  = tid >> 5;
    const int wm   = wid >> 1;        // 0..3 (32-row slice)
    const int wn   = wid & 1;         // 0..1 (32-col slice)

    const __nv_bfloat16* pAhi = g_Ahi + (size_t)m0 * Ddim;
    const __nv_bfloat16* pAlo = g_Alo + (size_t)m0 * Ddim;
    const __nv_bfloat16* pBhi = g_Bhi + (size_t)n0 * Ddim;
    const __nv_bfloat16* pBlo = g_Blo + (size_t)n0 * Ddim;

    uint32_t aoff[2];
#pragma unroll
    for (int mt = 0; mt < 2; mt++) {
        int row = wm * 32 + mt * 16 + (lane & 15);
        int phys = (lane >> 4) ^ ((row >> 1) & 3);
        aoff[mt] = (uint32_t)(A_HI + row * 64 + phys * 16);
    }
    uint32_t boff[2];
#pragma unroll
    for (int p = 0; p < 2; p++) {
        int row = wn * 32 + p * 16 + (((lane >> 4) & 1) << 3) + (lane & 7);
        int phys = ((lane >> 3) & 1) ^ ((row >> 1) & 3);
        boff[p] = (uint32_t)(B_HI + row * 64 + phys * 16);
    }

    float d[2][4][4];
#pragma unroll
    for (int mt = 0; mt < 2; mt++)
#pragma unroll
        for (int nt = 0; nt < 4; nt++)
#pragma unroll
            for (int q = 0; q < 4; q++) d[mt][nt][q] = 0.f;

#define FILL_STAGE(stg_base, koff)                                              \
    {                                                                           \
        _Pragma("unroll")                                                       \
        for (int t = 0; t < 6; t++) {                                           \
            int local; uint32_t abase; const __nv_bfloat16* gbase;              \
            if (t < 2)      { local = tid + t * 256;       abase = A_HI; gbase = pAhi; } \
            else if (t < 4) { local = tid + (t - 2) * 256; abase = A_LO; gbase = pAlo; } \
            else if (t == 4){ local = tid;                 abase = B_HI; gbase = pBhi; } \
            else            { local = tid;                 abase = B_LO; gbase = pBlo; } \
            int row  = local >> 2;                                              \
            int ch   = local & 3;                                               \
            int phys = ch ^ ((row >> 1) & 3);                                   \
            cp16((stg_base) + abase + (uint32_t)(row * 64 + phys * 16),         \
                 gbase + (size_t)row * Ddim + ch * 8 + (koff));                 \
        }                                                                       \
    }

#pragma unroll
    for (int ck = 0; ck < 2; ck++) {
        uint32_t stg = sb + ck * STGB;
        FILL_STAGE(stg, ck * 32);
        cp_commit();
    }

    for (int c = 0; c < NCHUNK; c++) {
        if (c + 1 < NCHUNK) cp_wait1(); else cp_wait0();
        __syncthreads();

        if (c + 2 < NCHUNK) {
            uint32_t stg = sb + ((c + 2) % NSTG) * STGB;
            FILL_STAGE(stg, (c + 2) * 32);
            cp_commit();
        }

        const uint32_t s0 = sb + (c % NSTG) * STGB;
#pragma unroll
        for (int g = 0; g < 2; g++) {
            const uint32_t gx = (uint32_t)(g * 32);
            uint32_t ah[2][4], al[2][4], bh[2][4], bl[2][4];
#pragma unroll
            for (int mt = 0; mt < 2; mt++) {
                uint32_t ra = s0 + (aoff[mt] ^ gx);
                ldsm_x4(ra,            ah[mt][0], ah[mt][1], ah[mt][2], ah[mt][3]);
                ldsm_x4(ra + 8192,     al[mt][0], al[mt][1], al[mt][2], al[mt][3]);
            }
#pragma unroll
            for (int p = 0; p < 2; p++) {
                uint32_t rb = s0 + (boff[p] ^ gx);
                ldsm_x4(rb,            bh[p][0], bh[p][1], bh[p][2], bh[p][3]);
                ldsm_x4(rb + 4096,     bl[p][0], bl[p][1], bl[p][2], bl[p][3]);
            }
#pragma unroll
            for (int mt = 0; mt < 2; mt++)
#pragma unroll
                for (int p = 0; p < 2; p++)
#pragma unroll
                    for (int j = 0; j < 2; j++)
                        mma_bf16(d[mt][p * 2 + j], ah[mt], bh[p] + j * 2);
#pragma unroll
            for (int mt = 0; mt < 2; mt++)
#pragma unroll
                for (int p = 0; p < 2; p++)
#pragma unroll
                    for (int j = 0; j < 2; j++)
                        mma_bf16(d[mt][p * 2 + j], ah[mt], bl[p] + j * 2);
#pragma unroll
            for (int mt = 0; mt < 2; mt++)
#pragma unroll
                for (int p = 0; p < 2; p++)
#pragma unroll
                    for (int j = 0; j < 2; j++)
                        mma_bf16(d[mt][p * 2 + j], al[mt], bh[p] + j * 2);
        }
    }

#pragma unroll
    for (int mt = 0; mt < 2; mt++) {
        int r0 = m0 + wm * 32 + mt * 16 + (lane >> 2);
#pragma unroll
        for (int nt = 0; nt < 4; nt++) {
            int col = n0 + wn * 32 + nt * 8 + (lane & 3) * 2;
            float* p0 = g_C + (size_t)r0 * NPAD + col;
            float* p1 = g_C + (size_t)(r0 + 8) * NPAD + col;
            *(float2*)p0 = make_float2(d[mt][nt][0], d[mt][nt][1]);
            *(float2*)p1 = make_float2(d[mt][nt][2], d[mt][nt][3]);
        }
    }
}

// ================= 4. per-row logsumexp + rank counts =================
// One row per block. C row prefix staged coalesced into smem; logits computed
// once into registers; max pass and sum/count pass run from registers.
// Same per-thread k-order and tree shapes as before -> bitwise-identical results.
__global__ __launch_bounds__(256) void reduce_kernel(const int* __restrict__ perm) {
    __shared__ float sC[NPAD];        // 16 KB: staged C row prefix
    __shared__ float redf[256];
    __shared__ int   redi[256];

    const int i   = blockIdx.x;
    const int tid = threadIdx.x;
    const int ucnt = g_Ucnt;

    // coalesced stage of the live row prefix
    const float* Crow = g_C + (size_t)i * NPAD;
    for (int s = tid; s < ucnt; s += 256) sC[s] = Crow[s];
    __syncthreads();

    const float ni = g_ni[i];
    const float lp = g_plog[i];

    // compute all 8 logits once (Kneg/256 = 8 per thread)
    float l[8];
#pragma unroll
    for (int q = 0; q < 8; q++) {
        int k = tid + q * 256;
        int p = perm[k];
        bool sel = (p >= i);
        int slot  = sel ? g_map1[k] : g_map0[k];
        float njc = sel ? g_nj1[k] : g_nj0[k];
        l[q] = sC[slot] / fmaxf(ni * njc, EPSN) * 2.0f;
    }

    // pass 1: max (register sweep + tree)
    float tmax = lp;
#pragma unroll
    for (int q = 0; q < 8; q++) tmax = fmaxf(tmax, l[q]);
    redf[tid] = tmax;
    __syncthreads();
    for (int o = 128; o > 0; o >>= 1) {
        if (tid < o) redf[tid] = fmaxf(redf[tid], redf[tid + o]);
        __syncthreads();
    }
    const float M = redf[0];
    __syncthreads();

    // pass 2: sum exp + count(neg > pos), from registers
    float s = 0.f;
    int cnt = 0;
#pragma unroll
    for (int q = 0; q < 8; q++) {
        s += expf(l[q] - M);
        cnt += (l[q] > lp) ? 1 : 0;
    }
    redf[tid] = s;
    redi[tid] = cnt;
    __syncthreads();
    for (int o = 128; o > 0; o >>= 1) {
        if (tid < o) { redf[tid] += redf[tid + o]; redi[tid] += redi[tid + o]; }
        __syncthreads();
    }
    if (tid == 0) {
        g_loss[i] = M + logf(redf[0] + expf(lp - M)) - lp;
        g_cnt[i]  = redi[0];
    }
}

// ================= 5. final reduction + state cleanup =================
__global__ void final_kernel(float* __restrict__ out) {
    __shared__ float sf[1024];
    __shared__ int   s1[1024];
    __shared__ int   s5[1024];
    int tid = threadIdx.x;
    float s = 0.f;
    int c1 = 0, c5 = 0;
    for (int i = tid; i < Bsz; i += 1024) {
        s += g_loss[i];
        int c = g_cnt[i];
        c1 += (c == 0) ? 1 : 0;
        c5 += (c <= 4) ? 1 : 0;
    }
    sf[tid] = s; s1[tid] = c1; s5[tid] = c5;
    __syncthreads();
    for (int o = 512; o > 0; o >>= 1) {
        if (tid < o) { sf[tid] += sf[tid + o]; s1[tid] += s1[tid + o]; s5[tid] += s5[tid + o]; }
        __syncthreads();
    }
    if (tid == 0) {
        out[0] = sf[0] / (float)Bsz;
        out[1] = 100.0f * (float)s1[0] / (float)Bsz;
        out[2] = 100.0f * (float)s5[0] / (float)Bsz;
        g_Ucnt = 0;                               // self-clean for next replay
    }
    for (int i = tid; i < Bsz; i += 1024) g_mark[i] = 0;
}

// ================= launch =================
extern "C" void kernel_launch(void* const* d_in, const int* in_sizes, int n_in,
                              void* d_out, int out_size) {
    const float* zi   = (const float*)d_in[0];
    const float* zj   = (const float*)d_in[1];
    const int*   perm = (const int*)d_in[2];
    float* out = (float*)d_out;

    cudaFuncSetAttribute(gemm_bf16_kernel, cudaFuncAttributeMaxDynamicSharedMemorySize, SMEM_TOTAL);

    assign_kernel<<<2, 1024>>>(perm);                                // 0
    norms_kernel<<<Bsz / 8, 256>>>(zi, zj);                          // 1
    prep_kernel<<<ZI_BLOCKS + ZJ_BLOCKS + MAP_BLOCKS, 256>>>(zi, zj, perm); // 2
    dim3 g(NPAD / 64, Bsz / 128);                                    // 64 x 64
    gemm_bf16_kernel<<<g, 256, SMEM_TOTAL>>>();                      // 3  (ncu target)
    reduce_kernel<<<Bsz, 256>>>(perm);                               // 4
    final_kernel<<<1, 1024>>>(out);                                  // 5
}